// round 1
// baseline (speedup 1.0000x reference)
#include <cuda_runtime.h>
#include <math.h>

// ---------------------------------------------------------------------------
// AttentionModule: N=500000, S=128, H=64
//
// Math collapse:
//   softmax(keys@wk + const) == softmax(NS @ u),  u = embed_w @ (key_w @ wk)
//   weighted_embedding = (w @ NS) @ embed_w + embed_b
// One full pass over NS (256 MB) with online softmax + vector accumulator.
// Output layout: out[0:64] = weighted_embedding, out[64:64+N] = attention_weights
// ---------------------------------------------------------------------------

#define NMAX   (1 << 20)   // covers N = 500000
#define MAXB   2048
#define K1_BLOCKS 1184     // 8 blocks/SM on 148 SMs
#define K1_TPB    256

__device__ float d_u[128];
__device__ float d_s[NMAX];
__device__ float d_bm[MAXB];
__device__ float d_bz[MAXB];
__device__ float d_bp[MAXB * 128];
__device__ float d_gm;
__device__ float d_ginvZ;

// Kernel 0: u[r] = sum_j embed_w[r,j] * v[j],  v[j] = sum_h key_w[j,h]*attn_w[64+h]
__global__ void k0_prep(const float* __restrict__ embed_w,
                        const float* __restrict__ key_w,
                        const float* __restrict__ attn_w) {
    __shared__ float v[64];
    int t = threadIdx.x;  // 128 threads
    if (t < 64) {
        float acc = 0.0f;
        #pragma unroll 8
        for (int h = 0; h < 64; ++h) acc += key_w[t * 64 + h] * attn_w[64 + h];
        v[t] = acc;
    }
    __syncthreads();
    float acc = 0.0f;
    #pragma unroll 8
    for (int j = 0; j < 64; ++j) acc += embed_w[t * 64 + j] * v[j];
    d_u[t] = acc;
}

__device__ __forceinline__ void online_update(float& m, float& Z, float4& p,
                                              float s, const float4& x) {
    if (s <= m) {
        float e = __expf(s - m);
        Z += e;
        p.x += e * x.x; p.y += e * x.y; p.z += e * x.z; p.w += e * x.w;
    } else {
        float c = __expf(m - s);   // exp(-inf)=0 handles first iteration
        Z = Z * c + 1.0f;
        p.x = p.x * c + x.x; p.y = p.y * c + x.y;
        p.z = p.z * c + x.z; p.w = p.w * c + x.w;
        m = s;
    }
}

// Kernel 1: one warp per row batch. s_i = NS_i . u ; online softmax with
// vector accumulator p (128 floats per warp, 4 per lane).
__global__ void __launch_bounds__(K1_TPB, 8)
k1_main(const float* __restrict__ ns, int N, int chunk) {
    const int lane = threadIdx.x & 31;
    const int wib  = threadIdx.x >> 5;                 // warp in block
    const int gw   = blockIdx.x * (K1_TPB >> 5) + wib; // global warp id

    float4 u4 = *reinterpret_cast<const float4*>(d_u + lane * 4);

    float  m = -INFINITY, Z = 0.0f;
    float4 p = make_float4(0.f, 0.f, 0.f, 0.f);

    int start = gw * chunk;
    int end   = start + chunk;
    if (end > N) end = N;

    for (int i = start; i < end; i += 2) {
        const float4* r0 = reinterpret_cast<const float4*>(ns + (size_t)i * 128) + lane;
        bool has1 = (i + 1 < end);
        float4 x0 = __ldg(r0);
        float4 x1 = has1 ? __ldg(r0 + 32) : make_float4(0.f, 0.f, 0.f, 0.f);

        float s0 = x0.x * u4.x + x0.y * u4.y + x0.z * u4.z + x0.w * u4.w;
        float s1 = x1.x * u4.x + x1.y * u4.y + x1.z * u4.z + x1.w * u4.w;
        #pragma unroll
        for (int off = 16; off > 0; off >>= 1) {
            s0 += __shfl_xor_sync(0xFFFFFFFFu, s0, off);
            s1 += __shfl_xor_sync(0xFFFFFFFFu, s1, off);
        }
        if (lane == 0)          d_s[i]     = s0;
        if (has1 && lane == 1)  d_s[i + 1] = s1;

        online_update(m, Z, p, s0, x0);
        if (has1) online_update(m, Z, p, s1, x1);
    }

    // ---- block combine (8 warps) ----
    __shared__ float smx[8], szz[8], sp[8 * 128];
    if (lane == 0) { smx[wib] = m; szz[wib] = Z; }
    sp[wib * 128 + lane * 4 + 0] = p.x;
    sp[wib * 128 + lane * 4 + 1] = p.y;
    sp[wib * 128 + lane * 4 + 2] = p.z;
    sp[wib * 128 + lane * 4 + 3] = p.w;
    __syncthreads();

    float mb = -INFINITY;
    #pragma unroll
    for (int j = 0; j < 8; ++j) mb = fmaxf(mb, smx[j]);

    if (threadIdx.x < 128) {
        int r = threadIdx.x;
        float acc = 0.0f;
        #pragma unroll
        for (int j = 0; j < 8; ++j) {
            float mw = smx[j];
            float c  = (mw == -INFINITY) ? 0.0f : __expf(mw - mb);
            acc += sp[j * 128 + r] * c;
        }
        d_bp[blockIdx.x * 128 + r] = acc;
    }
    if (threadIdx.x == 0) {
        float zb = 0.0f;
        #pragma unroll
        for (int j = 0; j < 8; ++j) {
            float mw = smx[j];
            zb += (mw == -INFINITY) ? 0.0f : szz[j] * __expf(mw - mb);
        }
        d_bz[blockIdx.x] = zb;
        d_bm[blockIdx.x] = mb;
    }
}

// Kernel 2: single block. Combine block partials, compute weighted_embedding,
// publish global (m, 1/Z) for kernel 3.
__global__ void k2_combine(const float* __restrict__ embed_w,
                           const float* __restrict__ embed_b,
                           float* __restrict__ out, int B) {
    __shared__ float c[MAXB];
    __shared__ float red[256];
    __shared__ float P[128];
    int t = threadIdx.x;

    // global max
    float lm = -INFINITY;
    for (int b = t; b < B; b += 256) lm = fmaxf(lm, d_bm[b]);
    red[t] = lm; __syncthreads();
    for (int s = 128; s > 0; s >>= 1) {
        if (t < s) red[t] = fmaxf(red[t], red[t + s]);
        __syncthreads();
    }
    float gm = red[0];
    __syncthreads();

    // scale factors + Z
    float lz = 0.0f;
    for (int b = t; b < B; b += 256) {
        float mb = d_bm[b];
        float cb = (mb == -INFINITY) ? 0.0f : __expf(mb - gm);
        c[b] = cb;
        lz += d_bz[b] * cb;
    }
    red[t] = lz; __syncthreads();
    for (int s = 128; s > 0; s >>= 1) {
        if (t < s) red[t] += red[t + s];
        __syncthreads();
    }
    float Z = red[0];
    if (t == 0) { d_gm = gm; d_ginvZ = 1.0f / Z; }
    __syncthreads();

    // P[r] = (sum_b bp[b][r]*c[b]) / Z   (weighted mean of NS rows)
    if (t < 128) {
        float acc = 0.0f;
        for (int b = 0; b < B; ++b) acc += d_bp[b * 128 + t] * c[b];
        P[t] = acc / Z;
    }
    __syncthreads();

    // weighted_embedding[h] = sum_r P[r]*embed_w[r,h] + embed_b[h]
    if (t < 64) {
        float acc = embed_b[t];
        #pragma unroll 8
        for (int r = 0; r < 128; ++r) acc += P[r] * embed_w[r * 64 + t];
        out[t] = acc;
    }
}

// Kernel 3: attention_weights[i] = exp(s_i - m) / Z
__global__ void k3_weights(float* __restrict__ out, int N) {
    int i = blockIdx.x * blockDim.x + threadIdx.x;
    if (i < N) out[64 + i] = __expf(d_s[i] - d_gm) * d_ginvZ;
}

extern "C" void kernel_launch(void* const* d_in, const int* in_sizes, int n_in,
                              void* d_out, int out_size) {
    const float* embed_w = (const float*)d_in[2];
    const float* embed_b = (const float*)d_in[3];
    const float* key_w   = (const float*)d_in[4];
    const float* attn_w  = (const float*)d_in[8];
    const float* ns      = (const float*)d_in[1];
    float* out = (float*)d_out;

    int N = in_sizes[1] / 128;

    k0_prep<<<1, 128>>>(embed_w, key_w, attn_w);

    int totalWarps = K1_BLOCKS * (K1_TPB / 32);
    int chunk = (N + totalWarps - 1) / totalWarps;
    k1_main<<<K1_BLOCKS, K1_TPB>>>(ns, N, chunk);

    k2_combine<<<1, 256>>>(embed_w, embed_b, out, K1_BLOCKS);

    k3_weights<<<(N + 255) / 256, 256>>>(out, N);
}

// round 2
// speedup vs baseline: 1.0211x; 1.0211x over previous
#include <cuda_runtime.h>
#include <math.h>

// ---------------------------------------------------------------------------
// AttentionModule: N=500000, S=128, H=64
//
// Math collapse:
//   softmax(keys@wk + const) == softmax(NS @ u),  u = embed_w @ (key_w @ wk)
//   weighted_embedding = (w @ NS) @ embed_w + embed_b
// One full pass over NS (256 MB) with online softmax + vector accumulator.
// Output layout: out[0:64] = weighted_embedding, out[64:64+N] = attention_weights
// ---------------------------------------------------------------------------

#define NMAX   (1 << 20)   // covers N = 500000
#define MAXB   2048
#define K1_BLOCKS 1184     // 8 blocks/SM on 148 SMs
#define K1_TPB    256

__device__ float d_u[128];
__device__ float d_s[NMAX];
__device__ float d_bm[MAXB];
__device__ float d_bz[MAXB];
__device__ float d_bp[MAXB * 128];
__device__ float d_gm;
__device__ float d_ginvZ;

// Kernel 0: u[r] = sum_j embed_w[r,j] * v[j],  v[j] = sum_h key_w[j,h]*attn_w[64+h]
__global__ void k0_prep(const float* __restrict__ embed_w,
                        const float* __restrict__ key_w,
                        const float* __restrict__ attn_w) {
    __shared__ float v[64];
    int t = threadIdx.x;  // 128 threads
    if (t < 64) {
        float acc = 0.0f;
        #pragma unroll 8
        for (int h = 0; h < 64; ++h) acc += key_w[t * 64 + h] * attn_w[64 + h];
        v[t] = acc;
    }
    __syncthreads();
    float acc = 0.0f;
    #pragma unroll 8
    for (int j = 0; j < 64; ++j) acc += embed_w[t * 64 + j] * v[j];
    d_u[t] = acc;
}

__device__ __forceinline__ void online_update(float& m, float& Z, float4& p,
                                              float s, const float4& x) {
    if (s <= m) {
        float e = __expf(s - m);
        Z += e;
        p.x += e * x.x; p.y += e * x.y; p.z += e * x.z; p.w += e * x.w;
    } else {
        float c = __expf(m - s);   // exp(-inf)=0 handles first iteration
        Z = Z * c + 1.0f;
        p.x = p.x * c + x.x; p.y = p.y * c + x.y;
        p.z = p.z * c + x.z; p.w = p.w * c + x.w;
        m = s;
    }
}

// Kernel 1: one warp per row batch. s_i = NS_i . u ; online softmax with
// vector accumulator p (128 floats per warp, 4 per lane).
__global__ void __launch_bounds__(K1_TPB, 8)
k1_main(const float* __restrict__ ns, int N, int chunk) {
    const int lane = threadIdx.x & 31;
    const int wib  = threadIdx.x >> 5;                 // warp in block
    const int gw   = blockIdx.x * (K1_TPB >> 5) + wib; // global warp id

    float4 u4 = *reinterpret_cast<const float4*>(d_u + lane * 4);

    float  m = -INFINITY, Z = 0.0f;
    float4 p = make_float4(0.f, 0.f, 0.f, 0.f);

    int start = gw * chunk;
    int end   = start + chunk;
    if (end > N) end = N;

    for (int i = start; i < end; i += 2) {
        const float4* r0 = reinterpret_cast<const float4*>(ns + (size_t)i * 128) + lane;
        bool has1 = (i + 1 < end);
        float4 x0 = __ldg(r0);
        float4 x1 = has1 ? __ldg(r0 + 32) : make_float4(0.f, 0.f, 0.f, 0.f);

        float s0 = x0.x * u4.x + x0.y * u4.y + x0.z * u4.z + x0.w * u4.w;
        float s1 = x1.x * u4.x + x1.y * u4.y + x1.z * u4.z + x1.w * u4.w;
        #pragma unroll
        for (int off = 16; off > 0; off >>= 1) {
            s0 += __shfl_xor_sync(0xFFFFFFFFu, s0, off);
            s1 += __shfl_xor_sync(0xFFFFFFFFu, s1, off);
        }
        if (lane == 0)          d_s[i]     = s0;
        if (has1 && lane == 1)  d_s[i + 1] = s1;

        online_update(m, Z, p, s0, x0);
        if (has1) online_update(m, Z, p, s1, x1);
    }

    // ---- block combine (8 warps) ----
    __shared__ float smx[8], szz[8], sp[8 * 128];
    if (lane == 0) { smx[wib] = m; szz[wib] = Z; }
    sp[wib * 128 + lane * 4 + 0] = p.x;
    sp[wib * 128 + lane * 4 + 1] = p.y;
    sp[wib * 128 + lane * 4 + 2] = p.z;
    sp[wib * 128 + lane * 4 + 3] = p.w;
    __syncthreads();

    float mb = -INFINITY;
    #pragma unroll
    for (int j = 0; j < 8; ++j) mb = fmaxf(mb, smx[j]);

    if (threadIdx.x < 128) {
        int r = threadIdx.x;
        float acc = 0.0f;
        #pragma unroll
        for (int j = 0; j < 8; ++j) {
            float mw = smx[j];
            float c  = (mw == -INFINITY) ? 0.0f : __expf(mw - mb);
            acc += sp[j * 128 + r] * c;
        }
        d_bp[blockIdx.x * 128 + r] = acc;
    }
    if (threadIdx.x == 0) {
        float zb = 0.0f;
        #pragma unroll
        for (int j = 0; j < 8; ++j) {
            float mw = smx[j];
            zb += (mw == -INFINITY) ? 0.0f : szz[j] * __expf(mw - mb);
        }
        d_bz[blockIdx.x] = zb;
        d_bm[blockIdx.x] = mb;
    }
}

// Kernel 2: single block. Combine block partials, compute weighted_embedding,
// publish global (m, 1/Z) for kernel 3.
__global__ void k2_combine(const float* __restrict__ embed_w,
                           const float* __restrict__ embed_b,
                           float* __restrict__ out, int B) {
    __shared__ float c[MAXB];
    __shared__ float red[256];
    __shared__ float P[128];
    int t = threadIdx.x;

    // global max
    float lm = -INFINITY;
    for (int b = t; b < B; b += 256) lm = fmaxf(lm, d_bm[b]);
    red[t] = lm; __syncthreads();
    for (int s = 128; s > 0; s >>= 1) {
        if (t < s) red[t] = fmaxf(red[t], red[t + s]);
        __syncthreads();
    }
    float gm = red[0];
    __syncthreads();

    // scale factors + Z
    float lz = 0.0f;
    for (int b = t; b < B; b += 256) {
        float mb = d_bm[b];
        float cb = (mb == -INFINITY) ? 0.0f : __expf(mb - gm);
        c[b] = cb;
        lz += d_bz[b] * cb;
    }
    red[t] = lz; __syncthreads();
    for (int s = 128; s > 0; s >>= 1) {
        if (t < s) red[t] += red[t + s];
        __syncthreads();
    }
    float Z = red[0];
    if (t == 0) { d_gm = gm; d_ginvZ = 1.0f / Z; }
    __syncthreads();

    // P[r] = (sum_b bp[b][r]*c[b]) / Z   (weighted mean of NS rows)
    if (t < 128) {
        float acc = 0.0f;
        for (int b = 0; b < B; ++b) acc += d_bp[b * 128 + t] * c[b];
        P[t] = acc / Z;
    }
    __syncthreads();

    // weighted_embedding[h] = sum_r P[r]*embed_w[r,h] + embed_b[h]
    if (t < 64) {
        float acc = embed_b[t];
        #pragma unroll 8
        for (int r = 0; r < 128; ++r) acc += P[r] * embed_w[r * 64 + t];
        out[t] = acc;
    }
}

// Kernel 3: attention_weights[i] = exp(s_i - m) / Z
__global__ void k3_weights(float* __restrict__ out, int N) {
    int i = blockIdx.x * blockDim.x + threadIdx.x;
    if (i < N) out[64 + i] = __expf(d_s[i] - d_gm) * d_ginvZ;
}

extern "C" void kernel_launch(void* const* d_in, const int* in_sizes, int n_in,
                              void* d_out, int out_size) {
    const float* embed_w = (const float*)d_in[2];
    const float* embed_b = (const float*)d_in[3];
    const float* key_w   = (const float*)d_in[4];
    const float* attn_w  = (const float*)d_in[8];
    const float* ns      = (const float*)d_in[1];
    float* out = (float*)d_out;

    int N = in_sizes[1] / 128;

    k0_prep<<<1, 128>>>(embed_w, key_w, attn_w);

    int totalWarps = K1_BLOCKS * (K1_TPB / 32);
    int chunk = (N + totalWarps - 1) / totalWarps;
    k1_main<<<K1_BLOCKS, K1_TPB>>>(ns, N, chunk);

    k2_combine<<<1, 256>>>(embed_w, embed_b, out, K1_BLOCKS);

    k3_weights<<<(N + 255) / 256, 256>>>(out, N);
}

// round 5
// speedup vs baseline: 1.0856x; 1.0632x over previous
#include <cuda_runtime.h>
#include <math.h>

// ---------------------------------------------------------------------------
// AttentionModule: N=500000, S=128, H=64
//
// Math collapse:
//   softmax(keys@wk + const) == softmax(NS @ u),  u = embed_w @ (key_w @ wk)
//   weighted_embedding = (w @ NS) @ embed_w + embed_b
// One pass over NS (256 MB) with online softmax + 128-float vector accumulator.
// out[0:64] = weighted_embedding, out[64:64+N] = attention_weights
// ---------------------------------------------------------------------------

#define NMAX   (1 << 20)
#define MAXB   2048
#define K1_BLOCKS 1184
#define K1_TPB    256

__device__ float d_u[128];
__device__ float d_s[NMAX];
__device__ float d_bm[MAXB];
__device__ float d_bz[MAXB];
__device__ float d_bp[MAXB * 128];
__device__ float d_gm;
__device__ float d_ginvZ;

// Kernel 0: u[r] = sum_j embed_w[r,j] * v[j],  v[j] = sum_h key_w[j,h]*attn_w[64+h]
__global__ void k0_prep(const float* __restrict__ embed_w,
                        const float* __restrict__ key_w,
                        const float* __restrict__ attn_w) {
    __shared__ float v[64];
    int t = threadIdx.x;  // 128 threads
    if (t < 64) {
        float acc = 0.0f;
        #pragma unroll 8
        for (int h = 0; h < 64; ++h) acc += key_w[t * 64 + h] * attn_w[64 + h];
        v[t] = acc;
    }
    __syncthreads();
    float acc = 0.0f;
    #pragma unroll 8
    for (int j = 0; j < 64; ++j) acc += embed_w[t * 64 + j] * v[j];
    d_u[t] = acc;
}

__device__ __forceinline__ float dot4(const float4& a, const float4& b) {
    return fmaf(a.x, b.x, fmaf(a.y, b.y, fmaf(a.z, b.z, a.w * b.w)));
}

// Kernel 1: one warp per row chunk, 4 rows per iteration, branchless merge.
__global__ void __launch_bounds__(K1_TPB)
k1_main(const float* __restrict__ ns, int N, int chunk) {
    const int lane = threadIdx.x & 31;
    const int wib  = threadIdx.x >> 5;
    const int gw   = blockIdx.x * (K1_TPB >> 5) + wib;

    float4 u4 = *reinterpret_cast<const float4*>(d_u + lane * 4);

    float  m = -INFINITY, Z = 0.0f;
    float4 p = make_float4(0.f, 0.f, 0.f, 0.f);

    int start = gw * chunk;
    int end   = start + chunk;
    if (start > N) start = N;
    if (end   > N) end   = N;

    const float4 zero4 = make_float4(0.f, 0.f, 0.f, 0.f);

    for (int i = start; i < end; i += 4) {
        const float4* r = reinterpret_cast<const float4*>(ns + (size_t)i * 128) + lane;
        int rem = end - i;   // >= 1

        float4 x0 = __ldcs(r);
        float4 x1 = (rem > 1) ? __ldcs(r + 32) : zero4;
        float4 x2 = (rem > 2) ? __ldcs(r + 64) : zero4;
        float4 x3 = (rem > 3) ? __ldcs(r + 96) : zero4;

        float s0 = dot4(x0, u4);
        float s1 = dot4(x1, u4);
        float s2 = dot4(x2, u4);
        float s3 = dot4(x3, u4);
        #pragma unroll
        for (int off = 16; off > 0; off >>= 1) {
            s0 += __shfl_xor_sync(0xFFFFFFFFu, s0, off);
            s1 += __shfl_xor_sync(0xFFFFFFFFu, s1, off);
            s2 += __shfl_xor_sync(0xFFFFFFFFu, s2, off);
            s3 += __shfl_xor_sync(0xFFFFFFFFu, s3, off);
        }
        if (lane == 0)            d_s[i]     = s0;
        if (lane == 1 && rem > 1) d_s[i + 1] = s1;
        if (lane == 2 && rem > 2) d_s[i + 2] = s2;
        if (lane == 3 && rem > 3) d_s[i + 3] = s3;

        // mask absent rows out of the softmax
        if (rem < 4) s3 = -INFINITY;
        if (rem < 3) s2 = -INFINITY;
        if (rem < 2) s1 = -INFINITY;

        float m4 = fmaxf(fmaxf(s0, s1), fmaxf(s2, s3));
        float e0 = __expf(s0 - m4);
        float e1 = __expf(s1 - m4);   // exp(-inf) = 0 for masked rows
        float e2 = __expf(s2 - m4);
        float e3 = __expf(s3 - m4);

        float  Z4 = (e0 + e1) + (e2 + e3);
        float4 p4;
        p4.x = fmaf(e0, x0.x, fmaf(e1, x1.x, fmaf(e2, x2.x, e3 * x3.x)));
        p4.y = fmaf(e0, x0.y, fmaf(e1, x1.y, fmaf(e2, x2.y, e3 * x3.y)));
        p4.z = fmaf(e0, x0.z, fmaf(e1, x1.z, fmaf(e2, x2.z, e3 * x3.z)));
        p4.w = fmaf(e0, x0.w, fmaf(e1, x1.w, fmaf(e2, x2.w, e3 * x3.w)));

        // branchless merge into running state
        float mn = fmaxf(m, m4);
        float cm = __expf(m  - mn);   // first iter: exp(-inf)=0
        float c4 = __expf(m4 - mn);
        Z   = fmaf(Z,   cm, Z4  * c4);
        p.x = fmaf(p.x, cm, p4.x * c4);
        p.y = fmaf(p.y, cm, p4.y * c4);
        p.z = fmaf(p.z, cm, p4.z * c4);
        p.w = fmaf(p.w, cm, p4.w * c4);
        m = mn;
    }

    // ---- block combine (8 warps) ----
    __shared__ float smx[8], szz[8], sp[8 * 128];
    if (lane == 0) { smx[wib] = m; szz[wib] = Z; }
    sp[wib * 128 + lane * 4 + 0] = p.x;
    sp[wib * 128 + lane * 4 + 1] = p.y;
    sp[wib * 128 + lane * 4 + 2] = p.z;
    sp[wib * 128 + lane * 4 + 3] = p.w;
    __syncthreads();

    float mb = -INFINITY;
    #pragma unroll
    for (int j = 0; j < 8; ++j) mb = fmaxf(mb, smx[j]);

    if (threadIdx.x < 128) {
        int r = threadIdx.x;
        float acc = 0.0f;
        #pragma unroll
        for (int j = 0; j < 8; ++j) {
            float mw = smx[j];
            float c  = (mw == -INFINITY) ? 0.0f : __expf(mw - mb);
            acc += sp[j * 128 + r] * c;
        }
        d_bp[blockIdx.x * 128 + r] = acc;
    }
    if (threadIdx.x == 0) {
        float zb = 0.0f;
        #pragma unroll
        for (int j = 0; j < 8; ++j) {
            float mw = smx[j];
            zb += (mw == -INFINITY) ? 0.0f : szz[j] * __expf(mw - mb);
        }
        d_bz[blockIdx.x] = zb;
        d_bm[blockIdx.x] = mb;
    }
}

// Kernel 2: single block, 1024 threads. Combine block partials, compute
// weighted_embedding, publish (m, 1/Z) for kernel 3.
__global__ void __launch_bounds__(1024)
k2_combine(const float* __restrict__ embed_w,
           const float* __restrict__ embed_b,
           float* __restrict__ out, int B) {
    __shared__ float c[MAXB];
    __shared__ float red[1024];
    __shared__ float P[128];
    int t = threadIdx.x;

    // global max over block maxima
    float lm = -INFINITY;
    for (int b = t; b < B; b += 1024) lm = fmaxf(lm, d_bm[b]);
    red[t] = lm; __syncthreads();
    for (int s = 512; s > 0; s >>= 1) {
        if (t < s) red[t] = fmaxf(red[t], red[t + s]);
        __syncthreads();
    }
    float gm = red[0];
    __syncthreads();

    // per-block scale factors + global Z
    float lz = 0.0f;
    for (int b = t; b < B; b += 1024) {
        float mb = d_bm[b];
        float cb = (mb == -INFINITY) ? 0.0f : __expf(mb - gm);
        c[b] = cb;
        lz += d_bz[b] * cb;
    }
    red[t] = lz; __syncthreads();
    for (int s = 512; s > 0; s >>= 1) {
        if (t < s) red[t] += red[t + s];
        __syncthreads();
    }
    float Z = red[0];
    if (t == 0) { d_gm = gm; d_ginvZ = 1.0f / Z; }
    __syncthreads();

    // P[r] = (sum_b bp[b][r]*c[b]) / Z  — 8-way parallel over b
    {
        int g = t >> 7;        // 0..7
        int r = t & 127;
        float acc = 0.0f;
        for (int b = g; b < B; b += 8)
            acc += d_bp[b * 128 + r] * c[b];
        red[t] = acc;
    }
    __syncthreads();
    if (t < 128) {
        float acc = 0.0f;
        #pragma unroll
        for (int g = 0; g < 8; ++g) acc += red[t + g * 128];
        P[t] = acc / Z;
    }
    __syncthreads();

    // weighted_embedding[h] = sum_r P[r]*embed_w[r,h] + embed_b[h]
    if (t < 64) {
        float acc = embed_b[t];
        #pragma unroll 8
        for (int r = 0; r < 128; ++r) acc += P[r] * embed_w[r * 64 + t];
        out[t] = acc;
    }
}

// Kernel 3: attention_weights[i] = exp(s_i - m) / Z  (float4 path)
__global__ void k3_weights(float* __restrict__ out, int N) {
    int i4 = (blockIdx.x * blockDim.x + threadIdx.x) * 4;
    float gm = d_gm, ginvZ = d_ginvZ;
    if (i4 + 3 < N) {
        float4 s = *reinterpret_cast<const float4*>(d_s + i4);
        float4 w;
        w.x = __expf(s.x - gm) * ginvZ;
        w.y = __expf(s.y - gm) * ginvZ;
        w.z = __expf(s.z - gm) * ginvZ;
        w.w = __expf(s.w - gm) * ginvZ;
        *reinterpret_cast<float4*>(out + 64 + i4) = w;
    } else {
        for (int i = i4; i < N; ++i)
            out[64 + i] = __expf(d_s[i] - gm) * ginvZ;
    }
}

extern "C" void kernel_launch(void* const* d_in, const int* in_sizes, int n_in,
                              void* d_out, int out_size) {
    const float* embed_w = (const float*)d_in[2];
    const float* embed_b = (const float*)d_in[3];
    const float* key_w   = (const float*)d_in[4];
    const float* attn_w  = (const float*)d_in[8];
    const float* ns      = (const float*)d_in[1];
    float* out = (float*)d_out;

    int N = in_sizes[1] / 128;

    k0_prep<<<1, 128>>>(embed_w, key_w, attn_w);

    int totalWarps = K1_BLOCKS * (K1_TPB / 32);
    int chunk = (N + totalWarps - 1) / totalWarps;
    chunk = (chunk + 3) & ~3;   // multiple of 4 for the unrolled loop
    k1_main<<<K1_BLOCKS, K1_TPB>>>(ns, N, chunk);

    k2_combine<<<1, 1024>>>(embed_w, embed_b, out, K1_BLOCKS);

    int n4 = (N + 3) / 4;
    k3_weights<<<(n4 + 255) / 256, 256>>>(out, N);
}

// round 7
// speedup vs baseline: 1.3141x; 1.2105x over previous
#include <cuda_runtime.h>
#include <math.h>

// ---------------------------------------------------------------------------
// AttentionModule: N=500000, S=128, H=64
//
//   softmax(keys@wk + const) == softmax(NS @ u),  u = embed_w @ (key_w @ wk)
//   weighted_embedding = (w @ NS) @ embed_w + embed_b
//
// k0: compute u, reset completion counter
// k1: block-contiguous streaming pass over NS (256 MB), online softmax with
//     128-float vector accumulator; last block combines partials, writes
//     weighted_embedding and publishes (gm, 1/Z)
// k3: normalize weights
// out[0:64] = weighted_embedding, out[64:64+N] = attention_weights
// ---------------------------------------------------------------------------

#define NMAX   (1 << 20)
#define K1_BLOCKS 592          // 4 blocks/SM x 148 SMs: exactly one wave
#define K1_TPB    256

__device__ float d_u[128];
__device__ float d_s[NMAX];
__device__ float d_bm[K1_BLOCKS];
__device__ float d_bz[K1_BLOCKS];
__device__ float d_bp[K1_BLOCKS * 128];
__device__ unsigned int d_ctr;
__device__ float d_gm;
__device__ float d_ginvZ;

// Kernel 0: u[r] = sum_j embed_w[r,j] * v[j],  v[j] = sum_h key_w[j,h]*attn_w[64+h]
__global__ void k0_prep(const float* __restrict__ embed_w,
                        const float* __restrict__ key_w,
                        const float* __restrict__ attn_w) {
    __shared__ float v[64];
    int t = threadIdx.x;  // 128 threads
    if (t == 0) d_ctr = 0u;
    if (t < 64) {
        float acc = 0.0f;
        #pragma unroll 8
        for (int h = 0; h < 64; ++h) acc += key_w[t * 64 + h] * attn_w[64 + h];
        v[t] = acc;
    }
    __syncthreads();
    float acc = 0.0f;
    #pragma unroll 8
    for (int j = 0; j < 64; ++j) acc += embed_w[t * 64 + j] * v[j];
    d_u[t] = acc;
}

__device__ __forceinline__ float dot4(const float4& a, const float4& b) {
    return fmaf(a.x, b.x, fmaf(a.y, b.y, fmaf(a.z, b.z, a.w * b.w)));
}

// Kernel 1: block-contiguous streaming. Block b owns rows [b*rpb, b*rpb+rpb).
// Within a 32-row tile, warp w handles rows tile+4w .. tile+4w+3, so the block
// sweeps a contiguous 16KB window forward (few, sequential DRAM streams).
__global__ void __launch_bounds__(K1_TPB, 4)
k1_main(const float* __restrict__ ns, int N, int rpb,
        const float* __restrict__ embed_w,
        const float* __restrict__ embed_b,
        float* __restrict__ out) {
    const int lane = threadIdx.x & 31;
    const int wib  = threadIdx.x >> 5;

    float4 u4 = *reinterpret_cast<const float4*>(d_u + lane * 4);

    float  m = -INFINITY, Z = 0.0f;
    float4 p = make_float4(0.f, 0.f, 0.f, 0.f);

    int bstart = blockIdx.x * rpb;
    int bend   = bstart + rpb;
    if (bstart > N) bstart = N;
    if (bend   > N) bend   = N;

    const float4 zero4 = make_float4(0.f, 0.f, 0.f, 0.f);

    for (int i = bstart + wib * 4; i < bend; i += 32) {
        const float4* r = reinterpret_cast<const float4*>(ns + (size_t)i * 128) + lane;
        int rows = bend - i;  // >= 1
        if (rows > 4) rows = 4;

        float4 x0 = __ldcs(r);
        float4 x1 = (rows > 1) ? __ldcs(r + 32) : zero4;
        float4 x2 = (rows > 2) ? __ldcs(r + 64) : zero4;
        float4 x3 = (rows > 3) ? __ldcs(r + 96) : zero4;

        float s0 = dot4(x0, u4);
        float s1 = dot4(x1, u4);
        float s2 = dot4(x2, u4);
        float s3 = dot4(x3, u4);
        #pragma unroll
        for (int off = 16; off > 0; off >>= 1) {
            s0 += __shfl_xor_sync(0xFFFFFFFFu, s0, off);
            s1 += __shfl_xor_sync(0xFFFFFFFFu, s1, off);
            s2 += __shfl_xor_sync(0xFFFFFFFFu, s2, off);
            s3 += __shfl_xor_sync(0xFFFFFFFFu, s3, off);
        }

        // single 4-lane contiguous store of the raw scores
        float sv = (lane == 0) ? s0 : (lane == 1) ? s1 : (lane == 2) ? s2 : s3;
        if (lane < rows) d_s[i + lane] = sv;

        // mask absent rows out of the softmax
        if (rows < 4) s3 = -INFINITY;
        if (rows < 3) s2 = -INFINITY;
        if (rows < 2) s1 = -INFINITY;

        float m4 = fmaxf(fmaxf(s0, s1), fmaxf(s2, s3));
        float e0 = __expf(s0 - m4);
        float e1 = __expf(s1 - m4);   // exp(-inf) = 0 for masked rows
        float e2 = __expf(s2 - m4);
        float e3 = __expf(s3 - m4);

        float  Z4 = (e0 + e1) + (e2 + e3);
        float4 p4;
        p4.x = fmaf(e0, x0.x, fmaf(e1, x1.x, fmaf(e2, x2.x, e3 * x3.x)));
        p4.y = fmaf(e0, x0.y, fmaf(e1, x1.y, fmaf(e2, x2.y, e3 * x3.y)));
        p4.z = fmaf(e0, x0.z, fmaf(e1, x1.z, fmaf(e2, x2.z, e3 * x3.z)));
        p4.w = fmaf(e0, x0.w, fmaf(e1, x1.w, fmaf(e2, x2.w, e3 * x3.w)));

        // branchless merge into running state
        float mn = fmaxf(m, m4);
        float cm = __expf(m  - mn);   // first iter: exp(-inf)=0
        float c4 = __expf(m4 - mn);
        Z   = fmaf(Z,   cm, Z4  * c4);
        p.x = fmaf(p.x, cm, p4.x * c4);
        p.y = fmaf(p.y, cm, p4.y * c4);
        p.z = fmaf(p.z, cm, p4.z * c4);
        p.w = fmaf(p.w, cm, p4.w * c4);
        m = mn;
    }

    // ---- block combine (8 warps) ----
    __shared__ float smx[8], szz[8], sp[8 * 128];
    if (lane == 0) { smx[wib] = m; szz[wib] = Z; }
    sp[wib * 128 + lane * 4 + 0] = p.x;
    sp[wib * 128 + lane * 4 + 1] = p.y;
    sp[wib * 128 + lane * 4 + 2] = p.z;
    sp[wib * 128 + lane * 4 + 3] = p.w;
    __syncthreads();

    float mb = -INFINITY;
    #pragma unroll
    for (int j = 0; j < 8; ++j) mb = fmaxf(mb, smx[j]);

    if (threadIdx.x < 128) {
        int r = threadIdx.x;
        float acc = 0.0f;
        #pragma unroll
        for (int j = 0; j < 8; ++j) {
            float mw = smx[j];
            float c  = (mw == -INFINITY) ? 0.0f : __expf(mw - mb);
            acc += sp[j * 128 + r] * c;
        }
        d_bp[blockIdx.x * 128 + r] = acc;
    }
    if (threadIdx.x == 0) {
        float zb = 0.0f;
        #pragma unroll
        for (int j = 0; j < 8; ++j) {
            float mw = smx[j];
            zb += (mw == -INFINITY) ? 0.0f : szz[j] * __expf(mw - mb);
        }
        d_bz[blockIdx.x] = zb;
        d_bm[blockIdx.x] = mb;
    }

    // ---- last-block global combine (fused former k2) ----
    __threadfence();
    __syncthreads();
    __shared__ int lastFlag;
    if (threadIdx.x == 0)
        lastFlag = (atomicAdd(&d_ctr, 1u) == (unsigned)(gridDim.x - 1));
    __syncthreads();
    if (!lastFlag) return;
    __threadfence();

    const int G = gridDim.x;
    __shared__ float cc[K1_BLOCKS];
    __shared__ float red[K1_TPB];
    __shared__ float P[128];
    int t = threadIdx.x;

    // global max
    float lm = -INFINITY;
    for (int b = t; b < G; b += K1_TPB) lm = fmaxf(lm, d_bm[b]);
    red[t] = lm; __syncthreads();
    for (int s = K1_TPB / 2; s > 0; s >>= 1) {
        if (t < s) red[t] = fmaxf(red[t], red[t + s]);
        __syncthreads();
    }
    float gm = red[0];
    __syncthreads();

    // scale factors + global Z
    float lz = 0.0f;
    for (int b = t; b < G; b += K1_TPB) {
        float mb2 = d_bm[b];
        float cb  = (mb2 == -INFINITY) ? 0.0f : __expf(mb2 - gm);
        cc[b] = cb;
        lz += d_bz[b] * cb;
    }
    red[t] = lz; __syncthreads();
    for (int s = K1_TPB / 2; s > 0; s >>= 1) {
        if (t < s) red[t] += red[t + s];
        __syncthreads();
    }
    float Zg = red[0];
    if (t == 0) { d_gm = gm; d_ginvZ = 1.0f / Zg; }
    __syncthreads();

    // P[r] = (sum_b bp[b][r]*c[b]) / Z  — 2-way parallel over b
    {
        int g = t >> 7;      // 0..1
        int r = t & 127;
        float acc = 0.0f;
        for (int b = g; b < G; b += 2)
            acc += d_bp[b * 128 + r] * cc[b];
        red[t] = acc;
    }
    __syncthreads();
    if (t < 128) P[t] = (red[t] + red[t + 128]) / Zg;
    __syncthreads();

    // weighted_embedding[h] = sum_r P[r]*embed_w[r,h] + embed_b[h]
    if (t < 64) {
        float acc = embed_b[t];
        #pragma unroll 8
        for (int r = 0; r < 128; ++r) acc += P[r] * embed_w[r * 64 + t];
        out[t] = acc;
    }
}

// Kernel 3: attention_weights[i] = exp(s_i - m) / Z  (float4 path)
__global__ void k3_weights(float* __restrict__ out, int N) {
    int i4 = (blockIdx.x * blockDim.x + threadIdx.x) * 4;
    float gm = d_gm, ginvZ = d_ginvZ;
    if (i4 + 3 < N) {
        float4 s = *reinterpret_cast<const float4*>(d_s + i4);
        float4 w;
        w.x = __expf(s.x - gm) * ginvZ;
        w.y = __expf(s.y - gm) * ginvZ;
        w.z = __expf(s.z - gm) * ginvZ;
        w.w = __expf(s.w - gm) * ginvZ;
        *reinterpret_cast<float4*>(out + 64 + i4) = w;
    } else {
        for (int i = i4; i < N; ++i)
            out[64 + i] = __expf(d_s[i] - gm) * ginvZ;
    }
}

extern "C" void kernel_launch(void* const* d_in, const int* in_sizes, int n_in,
                              void* d_out, int out_size) {
    const float* embed_w = (const float*)d_in[2];
    const float* embed_b = (const float*)d_in[3];
    const float* key_w   = (const float*)d_in[4];
    const float* attn_w  = (const float*)d_in[8];
    const float* ns      = (const float*)d_in[1];
    float* out = (float*)d_out;

    int N = in_sizes[1] / 128;

    k0_prep<<<1, 128>>>(embed_w, key_w, attn_w);

    int rpb = (N + K1_BLOCKS - 1) / K1_BLOCKS;   // rows per block (contiguous)
    k1_main<<<K1_BLOCKS, K1_TPB>>>(ns, N, rpb, embed_w, embed_b, out);

    int n4 = (N + 3) / 4;
    k3_weights<<<(n4 + 255) / 256, 256>>>(out, N);
}